// round 17
// baseline (speedup 1.0000x reference)
#include <cuda_runtime.h>
#include <cuda_fp16.h>
#include <math.h>
#include <cstdint>

#define BB 512
#define HH 2048
#define EE 2048
#define TT 256
#define NG 8192    // 4*H, permuted: n' = hc*4 + gate (i,f,g,o)

// ------------------------------------------------------------------ state
// All mma operands stored PRE-SWIZZLED in 16KB tiles (128 rows x 64 k, swz128),
// tile index = (rowblock * 32 + kchunk). Bulk-copy loads them linearly.
__device__ __align__(128) __half g_h[2][BB * HH];
__device__ __align__(128) float  g_c[BB * HH];
__device__ __align__(128) __half g_w[NG * HH];
__device__ __align__(128) __half g_a0[BB * EE];      // emb, fp16 tiles
__device__ __align__(128) __half g_wemb[HH * EE];    // W_embed, fp16 tiles
__device__ __align__(128) float  g_bsum[NG];
__device__ __align__(128) float  g_wih0[NG];
__device__ __align__(128) float  g_wih1[NG];

// ------------------------------------------------------------------ helpers
#define LDSM4(r, a) \
    asm volatile("ldmatrix.sync.aligned.m8n8.x4.shared.b16 {%0,%1,%2,%3}, [%4];" \
        : "=r"((r)[0]), "=r"((r)[1]), "=r"((r)[2]), "=r"((r)[3]) : "r"(a))

#define MBAR_INIT(b, c)   asm volatile("mbarrier.init.shared.b64 [%0], %1;" :: "r"(b), "r"(c) : "memory")
#define MBAR_EXPECT_TX(b, n) asm volatile("mbarrier.arrive.expect_tx.shared.b64 _, [%0], %1;" :: "r"(b), "r"(n) : "memory")
#define MBAR_ARRIVE(b)    asm volatile("mbarrier.arrive.shared.b64 _, [%0];" :: "r"(b) : "memory")
#define FENCE_ASYNC()     asm volatile("fence.proxy.async.shared::cta;" ::: "memory")

#define BULK_G2S(dst, src, bytes, mbar) \
    asm volatile("cp.async.bulk.shared::cta.global.mbarrier::complete_tx::bytes [%0], [%1], %2, [%3];" \
        :: "r"(dst), "l"(src), "r"(bytes), "r"(mbar) : "memory")

#define MBAR_WAIT(bar, ph) do {                                                   \
    uint32_t _b = (bar), _p = (ph), _d;                                           \
    asm volatile("{\n\t.reg .pred p;\n\t"                                         \
        "mbarrier.try_wait.parity.acquire.cta.shared::cta.b64 p, [%1], %2;\n\t"   \
        "selp.b32 %0, 1, 0, p;\n\t}" : "=r"(_d) : "r"(_b), "r"(_p) : "memory");   \
    if (!_d) {                                                                    \
        asm volatile("{\n\t.reg .pred P1;\n\t"                                    \
            "W%=:\n\tmbarrier.try_wait.parity.acquire.cta.shared::cta.b64 P1, [%0], %1, 0x989680;\n\t" \
            "@P1 bra.uni D%=;\n\tbra.uni W%=;\n\tD%=:\n\t}"                       \
            :: "r"(_b), "r"(_p) : "memory");                                      \
    }                                                                             \
} while (0)

__device__ __forceinline__ uint32_t smem_u32(const void* p) {
    uint32_t a;
    asm("{ .reg .u64 t; cvta.to.shared.u64 t, %1; cvt.u32.u64 %0, t; }" : "=r"(a) : "l"(p));
    return a;
}

__device__ __forceinline__ void mma16816(float* d, const uint32_t* a, const uint32_t* b) {
    asm volatile(
        "mma.sync.aligned.m16n8k16.row.col.f32.f16.f16.f32 "
        "{%0,%1,%2,%3}, {%4,%5,%6,%7}, {%8,%9}, {%0,%1,%2,%3};"
        : "+f"(d[0]), "+f"(d[1]), "+f"(d[2]), "+f"(d[3])
        : "r"(a[0]), "r"(a[1]), "r"(a[2]), "r"(a[3]), "r"(b[0]), "r"(b[1]));
}

// fast HW tanh (sm_75+); sigmoid via tanh identity
__device__ __forceinline__ float tanh_fast(float x) {
    float y;
    asm("tanh.approx.f32 %0, %1;" : "=f"(y) : "f"(x));
    return y;
}
__device__ __forceinline__ float sigm_fast(float x) {
    return fmaf(tanh_fast(0.5f * x), 0.5f, 0.5f);
}
__device__ __forceinline__ float sigm_acc(float x) { return 1.0f / (1.0f + __expf(-x)); }

// element offset (in halves) within a 16KB tile for (row 0..127, k 0..63)
__device__ __forceinline__ uint32_t tile_off(int row, int k) {
    int c8 = k >> 3;
    return (uint32_t)(row * 64 + ((((c8) ^ (row & 7)) & 7) << 3) + (k & 7));
}

// ------------------------------------------------------------------ prep
__global__ void prep_w_kernel(const float* __restrict__ W_hh) {
    int np = blockIdx.x;                 // 0..NG-1 (gate-interleaved row)
    int g = np & 3, hc = np >> 2;
    const float* src = W_hh + (size_t)(g * HH + hc) * HH;
    int nt = np >> 7, row = np & 127;
#pragma unroll
    for (int j = 0; j < HH / 256; j++) {
        int k = threadIdx.x + j * 256;
        size_t idx = (size_t)(nt * 32 + (k >> 6)) * 8192 + tile_off(row, k & 63);
        g_w[idx] = __float2half_rn(src[k]);
    }
}

// emb [BB, EE] -> fp16 tiles; W_embed [HH, EE] -> fp16 tiles
__global__ void prep_h0_kernel(const float* __restrict__ emb, const float* __restrict__ W_embed) {
    int r = blockIdx.x;
    const float* src;
    __half* dst;
    int row = r & 127, blk = r >> 7;
    if (r < BB) {
        src = emb + (size_t)r * EE;
        dst = g_a0;
    } else {
        int n = r - BB;
        src = W_embed + (size_t)n * EE;
        dst = g_wemb;
        row = n & 127; blk = n >> 7;
    }
#pragma unroll
    for (int j = 0; j < EE / 256; j++) {
        int k = threadIdx.x + j * 256;
        size_t idx = (size_t)(blk * 32 + (k >> 6)) * 8192 + tile_off(row, k & 63);
        dst[idx] = __float2half_rn(src[k]);
    }
}

__global__ void prep_misc_kernel(const float* __restrict__ b_ih, const float* __restrict__ b_hh,
                                 const float* __restrict__ W_ih) {
    int np = blockIdx.x * 256 + threadIdx.x;
    int g = np & 3, hc = np >> 2;
    int j = g * HH + hc;
    g_bsum[np] = b_ih[j] + b_hh[j];
    g_wih0[np] = W_ih[2 * j + 0];
    g_wih1[np] = W_ih[2 * j + 1];
}

__global__ void zero_out_kernel(float* __restrict__ out) {
    int i = blockIdx.x * 256 + threadIdx.x;
    if (i < BB * TT * 3) out[i] = 0.0f;
}

__global__ void stop_final_kernel(float* __restrict__ out, const float* __restrict__ b_stop) {
    int i = blockIdx.x * 256 + threadIdx.x;
    if (i < BB * TT) {
        float v = out[BB * TT * 2 + i];
        out[BB * TT * 2 + i] = sigm_acc(v + b_stop[0]);
    }
}

// ------------------------------------------------------------------ h0 via fp16 mma (128x128 tiles)
#define H0_NCHUNK 32
#define H0_A_OFF    0
#define H0_B_OFF    16384
#define H0_STAGE_BYTES 32768
#define H0_BIAS_OFF 0       // 128 floats
#define H0_BAR_OFF  1024
#define H0_STAGE0   4096
#define H0_SMEM     (H0_STAGE0 + 3 * H0_STAGE_BYTES)

__global__ __launch_bounds__(256, 2)
void h0_mma(const float* __restrict__ b_embed) {
    extern __shared__ char smem[];
    float* bias_s = (float*)(smem + H0_BIAS_OFF);
    int tid = threadIdx.x;
    int wid = tid >> 5, lane = tid & 31;
    int g = lane >> 2, tig = lane & 3;
    int wm = wid & 1, wn = wid >> 1;
    int n0 = blockIdx.x * 128, m0 = blockIdx.y * 128;
    uint32_t sbase = smem_u32(smem + H0_STAGE0);
    uint32_t fullb = smem_u32(smem + H0_BAR_OFF);
    uint32_t emptb = fullb + 24;

    const __half* atiles = g_a0 + (size_t)(blockIdx.y * 32) * 8192;
    const __half* btiles = g_wemb + (size_t)(blockIdx.x * 32) * 8192;

    if (tid == 0) {
#pragma unroll
        for (int s = 0; s < 3; s++) {
            MBAR_INIT(fullb + s * 8, 1);
            MBAR_INIT(emptb + s * 8, 8);
        }
        FENCE_ASYNC();
#pragma unroll
        for (int c = 0; c < 2; c++) {
            uint32_t st = sbase + c * H0_STAGE_BYTES;
            MBAR_EXPECT_TX(fullb + c * 8, (uint32_t)H0_STAGE_BYTES);
            BULK_G2S(st + H0_A_OFF, atiles + (size_t)c * 8192, 16384u, fullb + c * 8);
            BULK_G2S(st + H0_B_OFF, btiles + (size_t)c * 8192, 16384u, fullb + c * 8);
        }
    }

    int arow[4];
#pragma unroll
    for (int mi = 0; mi < 4; mi++) arow[mi] = wm * 64 + mi * 16 + (lane & 15);
    int abit = lane >> 4;
    int brow[2];
#pragma unroll
    for (int nip = 0; nip < 2; nip++)
        brow[nip] = wn * 32 + nip * 16 + ((lane >> 4) << 3) + (lane & 7);
    int bbit = (lane >> 3) & 1;

    uint32_t abase[4], asw[4], bbase[2], bsw[2];
#pragma unroll
    for (int mi = 0; mi < 4; mi++) { abase[mi] = arow[mi] * 128; asw[mi] = arow[mi] & 7; }
#pragma unroll
    for (int nip = 0; nip < 2; nip++) { bbase[nip] = brow[nip] * 128; bsw[nip] = brow[nip] & 7; }

    if (tid < 128) bias_s[tid] = b_embed[n0 + tid];
    __syncthreads();

    float acc[4][4][4];
#pragma unroll
    for (int mi = 0; mi < 4; mi++)
#pragma unroll
        for (int ni = 0; ni < 4; ni++)
#pragma unroll
            for (int j = 0; j < 4; j++) acc[mi][ni][j] = 0.0f;

    for (int c = 0; c < H0_NCHUNK; c++) {
        int s = c % 3;
        if (tid == 0 && c + 2 < H0_NCHUNK) {
            int q = c + 2, s2 = q % 3;
            if (q >= 3) MBAR_WAIT(emptb + s2 * 8, (q / 3 - 1) & 1);
            uint32_t st = sbase + s2 * H0_STAGE_BYTES;
            MBAR_EXPECT_TX(fullb + s2 * 8, (uint32_t)H0_STAGE_BYTES);
            BULK_G2S(st + H0_A_OFF, atiles + (size_t)q * 8192, 16384u, fullb + s2 * 8);
            BULK_G2S(st + H0_B_OFF, btiles + (size_t)q * 8192, 16384u, fullb + s2 * 8);
        }
        MBAR_WAIT(fullb + s * 8, (c / 3) & 1);

        uint32_t stage = sbase + s * H0_STAGE_BYTES;
#pragma unroll
        for (int kk = 0; kk < 4; kk++) {
            uint32_t ah[4][4];
#pragma unroll
            for (int mi = 0; mi < 4; mi++) {
                int cc = kk * 2 + abit;
                uint32_t ao = abase[mi] + (((cc ^ asw[mi]) & 7) << 4);
                LDSM4(ah[mi], stage + H0_A_OFF + ao);
            }
#pragma unroll
            for (int nip = 0; nip < 2; nip++) {
                int cc = kk * 2 + bbit;
                uint32_t bo = bbase[nip] + (((cc ^ bsw[nip]) & 7) << 4);
                uint32_t bh[4];
                LDSM4(bh, stage + H0_B_OFF + bo);
#pragma unroll
                for (int ni2 = 0; ni2 < 2; ni2++)
#pragma unroll
                    for (int mi = 0; mi < 4; mi++)
                        mma16816(acc[mi][nip * 2 + ni2], ah[mi], bh + ni2 * 2);
            }
        }
        if (lane == 0) MBAR_ARRIVE(emptb + s * 8);
    }

    __half* hdst = g_h[0];
#pragma unroll
    for (int mi = 0; mi < 4; mi++) {
        int r0 = wm * 64 + mi * 16 + g;
#pragma unroll
        for (int ni = 0; ni < 4; ni++) {
            int col = wn * 32 + ni * 8 + 2 * tig;
            int n = n0 + col;
            float b0 = bias_s[col], b1 = bias_s[col + 1];
            size_t tile0 = (size_t)((m0 >> 7) * 32 + (n >> 6)) * 8192;
            size_t tile1 = (size_t)((m0 >> 7) * 32 + ((n + 1) >> 6)) * 8192;
#pragma unroll
            for (int rr = 0; rr < 2; rr++) {
                int rl = r0 + rr * 8;
                float v0 = acc[mi][ni][rr * 2 + 0] + b0;
                float v1 = acc[mi][ni][rr * 2 + 1] + b1;
                hdst[tile0 + tile_off(rl, n & 63)] = __float2half_rn(v0);
                hdst[tile1 + tile_off(rl, (n + 1) & 63)] = __float2half_rn(v1);
            }
        }
    }
}

// ------------------------------------------------------------------ main LSTM step
// CTA tile: 128 M x 256 N, 512 threads = 16 warps (2 m x 8 n of 64x32).
// Grid (32, 4) = 128 CTAs, occ 1. BKC=64, 3-stage bulk-copy pipeline.
// 25% less L2 traffic than 128x128 tiling.
#define NCHUNK 32        // 2048 / 64
#define A_OFF    0
#define B_OFF    16384   // two 16KB B tiles back-to-back
#define STAGE_BYTES 49152
#define XS_OFF   0       // 128*2 floats = 1024B
#define SRED_OFF 1024    // 128*8*3 floats = 12288B -> ends 13312
#define BSP_OFF  13312   // 256 floats -> 14336
#define WAP_OFF  14336   // 256 floats -> 15360
#define WBP_OFF  15360   // 256 floats -> 16384
#define WH_OFF   16384   // 3*64 floats = 768 -> 17152
#define BAR_OFF  17152   // 6 mbarriers (48B)
#define STAGE0   17408
#define SMEM_TOTAL (STAGE0 + 3 * STAGE_BYTES)

__global__ __launch_bounds__(512, 1)
void lstm_step_mma(float* __restrict__ out, int t,
                   const float* __restrict__ W_out, const float* __restrict__ W_stop,
                   const float* __restrict__ b_out) {
    extern __shared__ char smem[];
    float* x_s  = (float*)(smem + XS_OFF);     // [128][2]
    float* sred = (float*)(smem + SRED_OFF);   // [128][8][3]
    float* bs_s = (float*)(smem + BSP_OFF);    // [256]
    float* wa_s = (float*)(smem + WAP_OFF);    // [256]
    float* wb_s = (float*)(smem + WBP_OFF);    // [256]
    float* w_s0 = (float*)(smem + WH_OFF);     // [64]
    float* w_s1 = w_s0 + 64;
    float* w_ss = w_s0 + 128;
    int tid = threadIdx.x;
    int wid = tid >> 5, lane = tid & 31;
    int g = lane >> 2, tig = lane & 3;
    int wm = wid & 1, wn = wid >> 1;            // 2 m-warps x 8 n-warps
    int n0 = blockIdx.x * 256, m0 = blockIdx.y * 128;
    int src = t & 1, dst = src ^ 1;
    uint32_t sbase = smem_u32(smem + STAGE0);
    uint32_t fullb = smem_u32(smem + BAR_OFF);          // full[0..2]
    uint32_t emptb = fullb + 24;                        // empty[0..2]

    const __half* atiles = g_h[src] + (size_t)(blockIdx.y * 32) * 8192;
    const __half* btiles0 = g_w + (size_t)(blockIdx.x * 2 * 32) * 8192;       // rows n0..n0+127
    const __half* btiles1 = g_w + (size_t)((blockIdx.x * 2 + 1) * 32) * 8192; // rows n0+128..n0+255

    // producer-side init + early prologue
    if (tid == 0) {
#pragma unroll
        for (int s = 0; s < 3; s++) {
            MBAR_INIT(fullb + s * 8, 1);
            MBAR_INIT(emptb + s * 8, 16);   // one arrive per warp
        }
        FENCE_ASYNC();
#pragma unroll
        for (int c = 0; c < 2; c++) {
            uint32_t st = sbase + c * STAGE_BYTES;
            MBAR_EXPECT_TX(fullb + c * 8, (uint32_t)STAGE_BYTES);
            BULK_G2S(st + A_OFF, atiles + (size_t)c * 8192, 16384u, fullb + c * 8);
            BULK_G2S(st + B_OFF,          btiles0 + (size_t)c * 8192, 16384u, fullb + c * 8);
            BULK_G2S(st + B_OFF + 16384,  btiles1 + (size_t)c * 8192, 16384u, fullb + c * 8);
        }
    }

    // ldmatrix lane mapping
    int arow[4];
#pragma unroll
    for (int mi = 0; mi < 4; mi++) arow[mi] = wm * 64 + mi * 16 + (lane & 15);
    int abit = lane >> 4;
    int brow[2];
#pragma unroll
    for (int nip = 0; nip < 2; nip++)
        brow[nip] = wn * 32 + nip * 16 + ((lane >> 4) << 3) + (lane & 7);   // 0..255
    int bbit = (lane >> 3) & 1;

    uint32_t abase[4], asw[4], bbase[2], bsw[2];
#pragma unroll
    for (int mi = 0; mi < 4; mi++) { abase[mi] = arow[mi] * 128; asw[mi] = arow[mi] & 7; }
#pragma unroll
    for (int nip = 0; nip < 2; nip++) {
        bbase[nip] = (uint32_t)((brow[nip] >> 7) * 16384 + (brow[nip] & 127) * 128);
        bsw[nip] = brow[nip] & 7;
    }

    // preload: prev coords, epilogue params, head weights
    if (tid < 128) {
        float x0 = 0.0f, x1 = 0.0f;
        if (t > 0) {
            x0 = out[((m0 + tid) * TT + t - 1) * 2 + 0];
            x1 = out[((m0 + tid) * TT + t - 1) * 2 + 1];
        }
        x_s[tid * 2 + 0] = x0;
        x_s[tid * 2 + 1] = x1;
    }
    if (tid < 256) {
        bs_s[tid] = g_bsum[n0 + tid];
        wa_s[tid] = g_wih0[n0 + tid];
        wb_s[tid] = g_wih1[n0 + tid];
    }
    if (tid < 64) {
        int hc = (n0 >> 2) + tid;
        w_s0[tid] = W_out[hc];
        w_s1[tid] = W_out[HH + hc];
        w_ss[tid] = W_stop[hc];
    }
    __syncthreads();    // mbarrier init + preload visible to all

    float acc[4][4][4];
#pragma unroll
    for (int mi = 0; mi < 4; mi++)
#pragma unroll
        for (int ni = 0; ni < 4; ni++)
#pragma unroll
            for (int j = 0; j < 4; j++) acc[mi][ni][j] = 0.0f;

    for (int c = 0; c < NCHUNK; c++) {
        int s = c % 3;
        if (tid == 0 && c + 2 < NCHUNK) {
            int q = c + 2, s2 = q % 3;
            if (q >= 3) MBAR_WAIT(emptb + s2 * 8, (q / 3 - 1) & 1);
            uint32_t st = sbase + s2 * STAGE_BYTES;
            MBAR_EXPECT_TX(fullb + s2 * 8, (uint32_t)STAGE_BYTES);
            BULK_G2S(st + A_OFF, atiles + (size_t)q * 8192, 16384u, fullb + s2 * 8);
            BULK_G2S(st + B_OFF,          btiles0 + (size_t)q * 8192, 16384u, fullb + s2 * 8);
            BULK_G2S(st + B_OFF + 16384,  btiles1 + (size_t)q * 8192, 16384u, fullb + s2 * 8);
        }
        MBAR_WAIT(fullb + s * 8, (c / 3) & 1);

        uint32_t stage = sbase + s * STAGE_BYTES;
#pragma unroll
        for (int kk = 0; kk < 4; kk++) {
            uint32_t ah[4][4];
#pragma unroll
            for (int mi = 0; mi < 4; mi++) {
                int cc = kk * 2 + abit;
                uint32_t ao = abase[mi] + (((cc ^ asw[mi]) & 7) << 4);
                LDSM4(ah[mi], stage + A_OFF + ao);
            }
#pragma unroll
            for (int nip = 0; nip < 2; nip++) {
                int cc = kk * 2 + bbit;
                uint32_t bo = bbase[nip] + (((cc ^ bsw[nip]) & 7) << 4);
                uint32_t bh[4];
                LDSM4(bh, stage + B_OFF + bo);
#pragma unroll
                for (int ni2 = 0; ni2 < 2; ni2++)
#pragma unroll
                    for (int mi = 0; mi < 4; mi++)
                        mma16816(acc[mi][nip * 2 + ni2], ah[mi], bh + ni2 * 2);
            }
        }
        if (lane == 0) MBAR_ARRIVE(emptb + s * 8);
    }

    // ------------------------------ fused LSTM epilogue + head partials
    __half* hdst = g_h[dst];
#pragma unroll
    for (int mi = 0; mi < 4; mi++) {
        int r0 = wm * 64 + mi * 16 + g;
        float hs[2][3] = {{0.0f, 0.0f, 0.0f}, {0.0f, 0.0f, 0.0f}};
#pragma unroll
        for (int ni = 0; ni < 4; ni++) {
            float o0 = acc[mi][ni][0], o1 = acc[mi][ni][1];
            float o2 = acc[mi][ni][2], o3 = acc[mi][ni][3];
            float p0 = __shfl_xor_sync(0xFFFFFFFFu, o0, 1);
            float p1 = __shfl_xor_sync(0xFFFFFFFFu, o1, 1);
            float p2 = __shfl_xor_sync(0xFFFFFFFFu, o2, 1);
            float p3 = __shfl_xor_sync(0xFFFFFFFFu, o3, 1);
            if ((tig & 1) == 0) {
                int col = wn * 32 + ni * 8 + 2 * tig;
                float4 bs = *(const float4*)&bs_s[col];
                float4 wa = *(const float4*)&wa_s[col];
                float4 wb = *(const float4*)&wb_s[col];
                int hc = (n0 + col) >> 2;
                int hcl = col >> 2;
                float w0v = w_s0[hcl], w1v = w_s1[hcl], wsv = w_ss[hcl];
                size_t htile = (size_t)((m0 >> 7) * 32 + (hc >> 6)) * 8192;
#pragma unroll
                for (int rr = 0; rr < 2; rr++) {
                    int rl = r0 + rr * 8;
                    int m = m0 + rl;
                    float x0 = x_s[rl * 2 + 0], x1 = x_s[rl * 2 + 1];
                    float vi = rr ? o2 : o0, vf = rr ? o3 : o1;
                    float vg = rr ? p2 : p0, vo = rr ? p3 : p1;
                    float pi = vi + bs.x + x0 * wa.x + x1 * wb.x;
                    float pf = vf + bs.y + x0 * wa.y + x1 * wb.y;
                    float pg = vg + bs.z + x0 * wa.z + x1 * wb.z;
                    float po = vo + bs.w + x0 * wa.w + x1 * wb.w;
                    float cp = (t == 0) ? 0.0f : g_c[m * HH + hc];
                    float cn = sigm_fast(pf) * cp + sigm_fast(pi) * tanh_fast(pg);
                    g_c[m * HH + hc] = cn;
                    float h = sigm_fast(po) * tanh_fast(cn);
                    hdst[htile + tile_off(rl, hc & 63)] = __float2half_rn(h);
                    hs[rr][0] += h * w0v;
                    hs[rr][1] += h * w1v;
                    hs[rr][2] += h * wsv;
                }
            }
        }
#pragma unroll
        for (int rr = 0; rr < 2; rr++) {
#pragma unroll
            for (int j = 0; j < 3; j++) {
                float v = hs[rr][j];
                v += __shfl_xor_sync(0xFFFFFFFFu, v, 2);
                if (tig == 0) sred[((r0 + rr * 8) * 8 + wn) * 3 + j] = v;
            }
        }
    }
    __syncthreads();
    if (tid < 128) {
        int m = m0 + tid;
        float s0 = 0.0f, s1 = 0.0f, s2 = 0.0f;
#pragma unroll
        for (int w = 0; w < 8; w++) {
            s0 += sred[(tid * 8 + w) * 3 + 0];
            s1 += sred[(tid * 8 + w) * 3 + 1];
            s2 += sred[(tid * 8 + w) * 3 + 2];
        }
        float b0 = 0.0f, b1 = 0.0f;
        if (blockIdx.x == 0) { b0 = b_out[0]; b1 = b_out[1]; }
        atomicAdd(&out[(m * TT + t) * 2 + 0], s0 + b0);
        atomicAdd(&out[(m * TT + t) * 2 + 1], s1 + b1);
        atomicAdd(&out[BB * TT * 2 + m * TT + t], s2);
    }
}

// ------------------------------------------------------------------ launch
extern "C" void kernel_launch(void* const* d_in, const int* in_sizes, int n_in,
                              void* d_out, int out_size) {
    const float* emb     = (const float*)d_in[0];
    const float* W_embed = (const float*)d_in[2];
    const float* b_embed = (const float*)d_in[3];
    const float* W_ih    = (const float*)d_in[4];
    const float* b_ih    = (const float*)d_in[5];
    const float* W_hh    = (const float*)d_in[6];
    const float* b_hh    = (const float*)d_in[7];
    const float* W_out   = (const float*)d_in[8];
    const float* b_out   = (const float*)d_in[9];
    const float* W_stop  = (const float*)d_in[10];
    const float* b_stop  = (const float*)d_in[11];
    float* out = (float*)d_out;

    cudaFuncSetAttribute(lstm_step_mma, cudaFuncAttributeMaxDynamicSharedMemorySize, SMEM_TOTAL);
    cudaFuncSetAttribute(h0_mma, cudaFuncAttributeMaxDynamicSharedMemorySize, H0_SMEM);

    zero_out_kernel<<<(BB * TT * 3 + 255) / 256, 256>>>(out);
    prep_w_kernel<<<NG, 256>>>(W_hh);
    prep_h0_kernel<<<BB + HH, 256>>>(emb, W_embed);
    prep_misc_kernel<<<NG / 256, 256>>>(b_ih, b_hh, W_ih);
    h0_mma<<<dim3(HH / 128, BB / 128), 256, H0_SMEM>>>(b_embed);

    for (int t = 0; t < TT; t++) {
        lstm_step_mma<<<dim3(32, 4), 512, SMEM_TOTAL>>>(out, t, W_out, W_stop, b_out);
    }
    stop_final_kernel<<<(BB * TT + 255) / 256, 256>>>(out, b_stop);
}